// round 8
// baseline (speedup 1.0000x reference)
#include <cuda_runtime.h>
#include <math.h>
#include <stdint.h>

#define NG   8192
#define SS   64
#define DD   128
#define HH   256
#define KK   8
#define GPB  8
#define NBATCH (NG / GPB)          // 1024
#define GRID   152                 // 1 block per SM (GB300: 152 SMs)
#define NSTAGE 4
#define RPS    8                   // rows per slice
#define NSLICE (SS / RPS)          // 8 slices per batch
#define EPSV 0.01f

#define OFF_MIX   (NG * DD)
#define OFF_SCALE (OFF_MIX + NG * KK)
#define OFF_ALPHA (OFF_SCALE + NG)
#define OFF_BETA  (OFF_ALPHA + NG)

// dynamic smem layout (bytes)
#define SM_MBAR_FULL   0                         // 4 x 8B
#define SM_MBAR_EMPTY  64                        // 4 x 8B
#define SM_XTILE       1024                      // 4 stages x 8 grp x 8 rows x 512B = 128 KB
#define SM_REP         (SM_XTILE + 131072)       // 8 KB  (double2[2][4][64])
#define SM_H           (SM_REP + 8192)           // 8 x 257 x 4 = 8224
#define SM_W2T         (SM_H + 8224)             // 10 x 256 x 4 = 10240
#define SM_TOTAL       (SM_W2T + 10240)          // ~158 KB

// named barriers: 1,2 = rep EMPTY[p], 3,4 = rep FULL[p], 5 = consumer-local
#define BAR_EMPTY(p) (1 + (p))
#define BAR_FULL(p)  (3 + (p))
#define BAR_CONS     5

__device__ __forceinline__ void bar_sync(int id, int cnt) {
    asm volatile("bar.sync %0, %1;" :: "r"(id), "r"(cnt) : "memory");
}
__device__ __forceinline__ void bar_arrive(int id, int cnt) {
    asm volatile("bar.arrive %0, %1;" :: "r"(id), "r"(cnt) : "memory");
}

// ---- mbarrier helpers ------------------------------------------------------
__device__ __forceinline__ void mbar_init(uint32_t a, uint32_t cnt) {
    asm volatile("mbarrier.init.shared.b64 [%0], %1;" :: "r"(a), "r"(cnt) : "memory");
}
__device__ __forceinline__ void mbar_expect_tx(uint32_t a, uint32_t bytes) {
    asm volatile("mbarrier.arrive.expect_tx.shared.b64 _, [%0], %1;"
                 :: "r"(a), "r"(bytes) : "memory");
}
__device__ __forceinline__ void mbar_arrive(uint32_t a) {
    asm volatile("mbarrier.arrive.shared.b64 _, [%0];" :: "r"(a) : "memory");
}
__device__ __forceinline__ void mbar_wait(uint32_t a, uint32_t parity) {
    asm volatile(
        "{\n\t.reg .pred P;\n"
        "WL_%=:\n\t"
        "mbarrier.try_wait.parity.acquire.cta.shared::cta.b64 P, [%0], %1, 0x989680;\n\t"
        "@P bra WD_%=;\n\t"
        "bra WL_%=;\n"
        "WD_%=:\n\t}"
        :: "r"(a), "r"(parity) : "memory");
}
__device__ __forceinline__ void tma_bulk_1d(uint32_t dst, const void* src,
                                            uint32_t bytes, uint32_t mbar) {
    asm volatile(
        "cp.async.bulk.shared::cta.global.mbarrier::complete_tx::bytes [%0], [%1], %2, [%3];"
        :: "r"(dst), "l"(src), "r"(bytes), "r"(mbar) : "memory");
}

// ---- packed f32x2 helpers (sm_103a) ----------------------------------------
__device__ __forceinline__ double add2(double a, double b) {
    double r; asm("add.rn.f32x2 %0,%1,%2;" : "=d"(r) : "d"(a), "d"(b)); return r;
}
__device__ __forceinline__ double fma2(double a, double b, double c) {
    double r; asm("fma.rn.f32x2 %0,%1,%2,%3;" : "=d"(r) : "d"(a), "d"(b), "d"(c)); return r;
}
__device__ __forceinline__ double pack2(float lo, float hi) {
    double r; asm("mov.b64 %0,{%1,%2};" : "=d"(r) : "f"(lo), "f"(hi)); return r;
}
__device__ __forceinline__ float2 unpack2(double v) {
    float2 r; asm("mov.b64 {%0,%1},%2;" : "=f"(r.x), "=f"(r.y) : "d"(v)); return r;
}
__device__ __forceinline__ float softplus_f(float v) {
    return v > 20.0f ? v : log1pf(expf(v));
}

__global__ __launch_bounds__(544, 1)
void tma_pipeline_kernel(
    const float* __restrict__ x,
    const float* __restrict__ y,
    const float* __restrict__ anchor_x,
    const float* __restrict__ anchor_y,
    const float* __restrict__ W1,
    const float* __restrict__ b1,
    const float* __restrict__ W2,
    const float* __restrict__ b2,
    float* __restrict__ out)
{
    extern __shared__ char smem[];
    const uint32_t smem_base =
        (uint32_t)__cvta_generic_to_shared(smem);

    float*  x_tile = (float*)(smem + SM_XTILE);                 // [stage][grp][row][128]
    double2 (*rep_buf)[GPB / 2][DD / 2] =
        (double2(*)[GPB / 2][DD / 2])(smem + SM_REP);           // [2][4][64]
    float (*h_s)[HH + 1] = (float(*)[HH + 1])(smem + SM_H);     // [8][257]
    float (*w2t)[HH]     = (float(*)[HH])(smem + SM_W2T);       // [10][256]

    const int tid = threadIdx.x;
    const int wid = tid >> 5;
    const int l   = tid & 31;

    // ---- init mbarriers ------------------------------------------------------
    if (tid == 0) {
        #pragma unroll
        for (int s = 0; s < NSTAGE; ++s) {
            mbar_init(smem_base + SM_MBAR_FULL  + 8 * s, 1);    // expect_tx arrival
            mbar_init(smem_base + SM_MBAR_EMPTY + 8 * s, 8);    // 8 stats warps
        }
    }
    if (wid >= 8 && wid < 16) {
        // consumers stage transposed W2 (ordered before use by BAR_CONS syncs)
        for (int i = tid - 256; i < HH * (KK + 2); i += 256) {
            int j = i / (KK + 2);
            int k = i - j * (KK + 2);
            w2t[k][j] = W2[i];
        }
    }
    __syncthreads();

    // ======================= TMA ISSUER (warp 16, lane 0) =====================
    if (tid == 512) {
        int lsf = 0;
        for (int B = blockIdx.x; B < NBATCH; B += GRID) {
            #pragma unroll
            for (int t = 0; t < NSLICE; ++t, ++lsf) {
                const int stage = lsf & (NSTAGE - 1);
                if (lsf >= NSTAGE)
                    mbar_wait(smem_base + SM_MBAR_EMPTY + 8 * stage,
                              ((lsf >> 2) + 1) & 1);
                const uint32_t full_a = smem_base + SM_MBAR_FULL + 8 * stage;
                mbar_expect_tx(full_a, GPB * RPS * DD * 4);     // 32 KB
                #pragma unroll
                for (int w = 0; w < GPB; ++w) {
                    const float* src = x + (size_t)(B * GPB + w) * SS * DD
                                         + t * RPS * DD;
                    const uint32_t dst = smem_base + SM_XTILE
                                       + stage * (GPB * RPS * DD * 4)
                                       + w * (RPS * DD * 4);
                    tma_bulk_1d(dst, src, RPS * DD * 4, full_a); // 4 KB
                }
            }
        }
        return;
    }
    if (wid == 16) return;   // other lanes of issuer warp idle

    const bool producer = (wid < 8);

    int ib = 0;
    int lsc = 0;             // stats-warp local slice counter
    for (int B = blockIdx.x; B < NBATCH; B += GRID, ++ib) {
        const int p = ib & 1;

        if (producer) {
            // ================= STATS warps 0..7 (group w of batch) =============
            const int w = wid;
            const int g = B * GPB + w;

            float4 a4 = reinterpret_cast<const float4*>(anchor_x + (size_t)g * DD)[l];
            const float ayv = anchor_y[g];
            const float* yg = y + (size_t)g * SS;
            float ya = yg[l]      - ayv;
            float yb = yg[32 + l] - ayv;

            const double na_lo = pack2(-a4.x, -a4.y);
            const double na_hi = pack2(-a4.z, -a4.w);

            double sx_lo = 0.0, sx_hi = 0.0;
            double sxy_lo = 0.0, sxy_hi = 0.0;
            double sxx2 = 0.0;
            float  sy = 0.f;

            #pragma unroll
            for (int t = 0; t < NSLICE; ++t, ++lsc) {
                const int stage = lsc & (NSTAGE - 1);
                mbar_wait(smem_base + SM_MBAR_FULL + 8 * stage, (lsc >> 2) & 1);

                const float* slice = x_tile + stage * (GPB * RPS * DD)
                                            + w * (RPS * DD) + 4 * l;
                const float ysrc = (t < 4) ? ya : yb;
                #pragma unroll
                for (int r = 0; r < RPS; ++r) {
                    float4 xv = *reinterpret_cast<const float4*>(slice + r * DD);
                    float yr = __shfl_sync(0xFFFFFFFFu, ysrc, (t * RPS + r) & 31);
                    double2 xd = *reinterpret_cast<double2*>(&xv);
                    double yr2 = pack2(yr, yr);
                    double xr_lo = add2(xd.x, na_lo);
                    double xr_hi = add2(xd.y, na_hi);
                    sx_lo  = add2(sx_lo, xr_lo);
                    sx_hi  = add2(sx_hi, xr_hi);
                    sxy_lo = fma2(xr_lo, yr2, sxy_lo);
                    sxy_hi = fma2(xr_hi, yr2, sxy_hi);
                    sxx2   = fma2(xr_lo, xr_lo, sxx2);
                    sxx2   = fma2(xr_hi, xr_hi, sxx2);
                    sy += yr;
                }
                if (l == 0) mbar_arrive(smem_base + SM_MBAR_EMPTY + 8 * stage);
            }

            float2 sxxp = unpack2(sxx2);
            float sxx = sxxp.x + sxxp.y;
            float2 sxl = unpack2(sx_lo),  sxh = unpack2(sx_hi);
            float2 syl = unpack2(sxy_lo), syh = unpack2(sxy_hi);
            float tot = sxl.x + sxl.y + sxh.x + sxh.y;

            #pragma unroll
            for (int o = 16; o > 0; o >>= 1) {
                sxx += __shfl_xor_sync(0xFFFFFFFFu, sxx, o);
                tot += __shfl_xor_sync(0xFFFFFFFFu, tot, o);
            }

            const float nD      = (float)(SS * DD);
            const float var     = (sxx - tot * tot / nD) / (nD - 1.0f);
            const float inv_var = 1.0f / var;
            const float c       = sy / (float)SS;
            const float inv_nm1 = 1.0f / (float)(SS - 1);

            float4 rep;
            rep.x = (syl.x - sxl.x * c) * inv_nm1 * inv_var;
            rep.y = (syl.y - sxl.y * c) * inv_nm1 * inv_var;
            rep.z = (syh.x - sxh.x * c) * inv_nm1 * inv_var;
            rep.w = (syh.y - sxh.y * c) * inv_nm1 * inv_var;

            reinterpret_cast<float4*>(out + (size_t)g * DD)[l] = rep;

            if (ib >= 2) bar_sync(BAR_EMPTY(p), 512);

            {
                const int pp  = w >> 1;
                const int sel = w & 1;
                float* base = reinterpret_cast<float*>(&rep_buf[p][pp][0]);
                base[2 * (4 * l + 0) + sel] = rep.x;
                base[2 * (4 * l + 1) + sel] = rep.y;
                base[2 * (4 * l + 2) + sel] = rep.z;
                base[2 * (4 * l + 3) + sel] = rep.w;
            }
            asm volatile("membar.cta;" ::: "memory");
            bar_arrive(BAR_FULL(p), 512);
        } else {
            // ================= MLP consumers (warps 8..15) =====================
            bar_sync(BAR_FULL(p), 512);

            const int j = tid - 256;
            {
                const float bj = b1[j];
                double acc[GPB / 2];
                #pragma unroll
                for (int pp = 0; pp < GPB / 2; ++pp) acc[pp] = pack2(bj, bj);

                #pragma unroll 4
                for (int d = 0; d < DD; d += 2) {
                    float w0  = W1[(d + 0) * HH + j];
                    float w1v = W1[(d + 1) * HH + j];
                    double wd0 = pack2(w0, w0);
                    double wd1 = pack2(w1v, w1v);
                    #pragma unroll
                    for (int pp = 0; pp < GPB / 2; ++pp) {
                        double2 rp = rep_buf[p][pp][d >> 1];
                        acc[pp] = fma2(rp.x, wd0, acc[pp]);
                        acc[pp] = fma2(rp.y, wd1, acc[pp]);
                    }
                }
                #pragma unroll
                for (int pp = 0; pp < GPB / 2; ++pp) {
                    float2 hv = unpack2(acc[pp]);
                    h_s[2 * pp + 0][j] = tanhf(hv.x);
                    h_s[2 * pp + 1][j] = tanhf(hv.y);
                }
            }
            bar_sync(BAR_CONS, 256);
            bar_arrive(BAR_EMPTY(p), 512);

            {
                const int w  = wid - 8;
                const int gl = B * GPB + w;

                float acc[KK + 2];
                #pragma unroll
                for (int k = 0; k < KK + 2; ++k) acc[k] = 0.f;

                #pragma unroll
                for (int t = 0; t < HH / 32; ++t) {
                    const int jj = 32 * t + l;
                    const float hv = h_s[w][jj];
                    #pragma unroll
                    for (int k = 0; k < KK + 2; ++k)
                        acc[k] = fmaf(hv, w2t[k][jj], acc[k]);
                }
                #pragma unroll
                for (int k = 0; k < KK + 2; ++k) {
                    #pragma unroll
                    for (int o = 16; o > 0; o >>= 1)
                        acc[k] += __shfl_xor_sync(0xFFFFFFFFu, acc[k], o);
                }

                if (l == 0) {
                    float o0 = acc[0] + b2[0];
                    float o1 = acc[1] + b2[1];
                    float alpha = softplus_f(o0) * (1.0f - EPSV) + EPSV;
                    float beta  = softplus_f(o1) * (1.0f - EPSV) + EPSV;

                    float ok[KK];
                    float m = -INFINITY;
                    #pragma unroll
                    for (int k = 0; k < KK; ++k) {
                        ok[k] = acc[2 + k] + b2[2 + k];
                        m = fmaxf(m, ok[k]);
                    }
                    float s = 0.f;
                    #pragma unroll
                    for (int k = 0; k < KK; ++k) { ok[k] = expf(ok[k] - m); s += ok[k]; }
                    float inv = 1.0f / s;
                    #pragma unroll
                    for (int k = 0; k < KK; ++k)
                        out[OFF_MIX + (size_t)gl * KK + k] = ok[k] * inv;

                    out[OFF_SCALE + gl] = sqrtf(beta / alpha);
                    out[OFF_ALPHA + gl] = alpha;
                    out[OFF_BETA  + gl] = beta;
                }
            }
        }
    }
}

extern "C" void kernel_launch(void* const* d_in, const int* in_sizes, int n_in,
                              void* d_out, int out_size) {
    // inputs (metadata order): index, x, y, anchor_x, anchor_y, W1, b1, W2, b2
    const float* x        = (const float*)d_in[1];
    const float* y        = (const float*)d_in[2];
    const float* anchor_x = (const float*)d_in[3];
    const float* anchor_y = (const float*)d_in[4];
    const float* W1       = (const float*)d_in[5];
    const float* b1       = (const float*)d_in[6];
    const float* W2       = (const float*)d_in[7];
    const float* b2       = (const float*)d_in[8];
    float* out            = (float*)d_out;

    static bool attr_set = false;
    if (!attr_set) {
        cudaFuncSetAttribute(tma_pipeline_kernel,
                             cudaFuncAttributeMaxDynamicSharedMemorySize, SM_TOTAL);
        attr_set = true;
    }
    tma_pipeline_kernel<<<GRID, 544, SM_TOTAL>>>(x, y, anchor_x, anchor_y,
                                                 W1, b1, W2, b2, out);
}

// round 9
// speedup vs baseline: 1.1788x; 1.1788x over previous
#include <cuda_runtime.h>
#include <math.h>
#include <stdint.h>

#define NG   8192
#define SS   64
#define DD   128
#define HH   256
#define KK   8
#define GPB  8
#define NBATCH (NG / GPB)           // 1024
#define GRID_B 304                  // 2 blocks/SM on 152 SMs
#define EPSV 0.01f

#define OFF_MIX   (NG * DD)
#define OFF_SCALE (OFF_MIX + NG * KK)
#define OFF_ALPHA (OFF_SCALE + NG)
#define OFF_BETA  (OFF_ALPHA + NG)

// dynamic smem layout (bytes)
#define RING_STAGE_B   2048                       // 4 rows x 512 B
#define RING_WARP_B    (4 * RING_STAGE_B)         // 8 KB per producer warp
#define SM_XRING       0                          // 8 warps x 8 KB = 64 KB
#define SM_REP         65536                      // double2[2][4][64] = 8 KB
#define SM_H           73728                      // [8][257] f32 = 8224
#define SM_W2T         81952                      // [10][256] f32 = 10240
#define SM_TOTAL       92192

// named barriers: 1,2 = rep EMPTY[p], 3,4 = rep FULL[p], 5 = consumer-local
#define BAR_EMPTY(p) (1 + (p))
#define BAR_FULL(p)  (3 + (p))
#define BAR_CONS     5
#define NT           384

__device__ __forceinline__ void bar_sync(int id, int cnt) {
    asm volatile("bar.sync %0, %1;" :: "r"(id), "r"(cnt) : "memory");
}
__device__ __forceinline__ void bar_arrive(int id, int cnt) {
    asm volatile("bar.arrive %0, %1;" :: "r"(id), "r"(cnt) : "memory");
}
__device__ __forceinline__ void cpasync16(uint32_t dst, const void* src) {
    asm volatile("cp.async.cg.shared.global [%0], [%1], 16;"
                 :: "r"(dst), "l"(src) : "memory");
}
__device__ __forceinline__ void cp_commit() {
    asm volatile("cp.async.commit_group;" ::: "memory");
}
__device__ __forceinline__ void cp_wait3() {
    asm volatile("cp.async.wait_group 3;" ::: "memory");
}

// ---- packed f32x2 helpers (sm_103a) ----------------------------------------
__device__ __forceinline__ double add2(double a, double b) {
    double r; asm("add.rn.f32x2 %0,%1,%2;" : "=d"(r) : "d"(a), "d"(b)); return r;
}
__device__ __forceinline__ double fma2(double a, double b, double c) {
    double r; asm("fma.rn.f32x2 %0,%1,%2,%3;" : "=d"(r) : "d"(a), "d"(b), "d"(c)); return r;
}
__device__ __forceinline__ double pack2(float lo, float hi) {
    double r; asm("mov.b64 %0,{%1,%2};" : "=d"(r) : "f"(lo), "f"(hi)); return r;
}
__device__ __forceinline__ float2 unpack2(double v) {
    float2 r; asm("mov.b64 {%0,%1},%2;" : "=f"(r.x), "=f"(r.y) : "d"(v)); return r;
}
__device__ __forceinline__ float softplus_f(float v) {
    return v > 20.0f ? v : log1pf(expf(v));
}

__global__ __launch_bounds__(NT, 2)
void casync_pipeline_kernel(
    const float* __restrict__ x,
    const float* __restrict__ y,
    const float* __restrict__ anchor_x,
    const float* __restrict__ anchor_y,
    const float* __restrict__ W1,
    const float* __restrict__ b1,
    const float* __restrict__ W2,
    const float* __restrict__ b2,
    float* __restrict__ out)
{
    extern __shared__ char smem[];
    const uint32_t smem_base = (uint32_t)__cvta_generic_to_shared(smem);

    double2 (*rep_buf)[GPB / 2][DD / 2] =
        (double2(*)[GPB / 2][DD / 2])(smem + SM_REP);
    float (*h_s)[HH + 1] = (float(*)[HH + 1])(smem + SM_H);
    float (*w2t)[HH]     = (float(*)[HH])(smem + SM_W2T);

    const int tid = threadIdx.x;
    const int wid = tid >> 5;
    const int l   = tid & 31;
    const bool producer = (wid < 8);

    if (!producer) {
        // consumers (128 threads) stage transposed W2; ordered by first BAR_CONS
        for (int i = tid - 256; i < HH * (KK + 2); i += 128) {
            int j = i / (KK + 2);
            int k = i - j * (KK + 2);
            w2t[k][j] = W2[i];
        }
    }
    __syncthreads();

    int ib = 0;
    for (int B = blockIdx.x; B < NBATCH; B += GRID_B, ++ib) {
        const int p = ib & 1;

        if (producer) {
            // ================= PRODUCER warp (group w of batch B) ==============
            const int w = wid;
            const int g = B * GPB + w;
            const uint32_t ring = smem_base + SM_XRING + w * RING_WARP_B + 16 * l;

            const float* xb = x + (size_t)g * SS * DD + 4 * l;   // this batch
            const int Bn = B + GRID_B;
            const float* xn = (Bn < NBATCH)                       // next batch (or dummy)
                ? x + ((size_t)Bn * GPB + w) * SS * DD + 4 * l
                : x + 4 * l;

            float4 a4 = reinterpret_cast<const float4*>(anchor_x + (size_t)g * DD)[l];
            const float ayv = anchor_y[g];
            const float* yg = y + (size_t)g * SS;
            float ya = yg[l]      - ayv;
            float yb = yg[32 + l] - ayv;

            const double na_lo = pack2(-a4.x, -a4.y);
            const double na_hi = pack2(-a4.z, -a4.w);

            double sx_lo = 0.0, sx_hi = 0.0;
            double sxy_lo = 0.0, sxy_hi = 0.0;
            double sxx2 = 0.0;
            float  sy = 0.f;

            // prologue (first batch only): fill ring slots 0..2 from this batch
            if (ib == 0) {
                #pragma unroll
                for (int s = 0; s < 3; ++s) {
                    #pragma unroll
                    for (int r = 0; r < 4; ++r)
                        cpasync16(ring + s * RING_STAGE_B + r * 512,
                                  xb + (4 * s + r) * DD);
                    cp_commit();
                }
            }

            #pragma unroll 4
            for (int t = 0; t < 16; ++t) {
                // issue stage t+3: rows of this batch, or first stages of next
                {
                    const float* src = (t < 13) ? (xb + (t + 3) * 4 * DD)
                                                : (xn + (t - 13) * 4 * DD);
                    const uint32_t dst = ring + ((t + 3) & 3) * RING_STAGE_B;
                    #pragma unroll
                    for (int r = 0; r < 4; ++r)
                        cpasync16(dst + r * 512, src + r * DD);
                    cp_commit();
                }
                cp_wait3();                       // stage t resident

                const char* slice = smem + SM_XRING + w * RING_WARP_B
                                  + (t & 3) * RING_STAGE_B + 16 * l;
                const float ysel = (t < 8) ? ya : yb;
                #pragma unroll
                for (int r = 0; r < 4; ++r) {
                    float4 xv = *reinterpret_cast<const float4*>(slice + r * 512);
                    float yr = __shfl_sync(0xFFFFFFFFu, ysel, (4 * t + r) & 31);
                    double2 xd = *reinterpret_cast<double2*>(&xv);
                    double yr2 = pack2(yr, yr);
                    double xr_lo = add2(xd.x, na_lo);
                    double xr_hi = add2(xd.y, na_hi);
                    sx_lo  = add2(sx_lo, xr_lo);
                    sx_hi  = add2(sx_hi, xr_hi);
                    sxy_lo = fma2(xr_lo, yr2, sxy_lo);
                    sxy_hi = fma2(xr_hi, yr2, sxy_hi);
                    sxx2   = fma2(xr_lo, xr_lo, sxx2);
                    sxx2   = fma2(xr_hi, xr_hi, sxx2);
                    sy += yr;
                }
            }

            float2 sxxp = unpack2(sxx2);
            float sxx = sxxp.x + sxxp.y;
            float2 sxl = unpack2(sx_lo),  sxh = unpack2(sx_hi);
            float2 syl = unpack2(sxy_lo), syh = unpack2(sxy_hi);
            float tot = sxl.x + sxl.y + sxh.x + sxh.y;

            #pragma unroll
            for (int o = 16; o > 0; o >>= 1) {
                sxx += __shfl_xor_sync(0xFFFFFFFFu, sxx, o);
                tot += __shfl_xor_sync(0xFFFFFFFFu, tot, o);
            }

            const float nD      = (float)(SS * DD);
            const float var     = (sxx - tot * tot / nD) / (nD - 1.0f);
            const float inv_var = 1.0f / var;
            const float c       = sy / (float)SS;
            const float inv_nm1 = 1.0f / (float)(SS - 1);

            float4 rep;
            rep.x = (syl.x - sxl.x * c) * inv_nm1 * inv_var;
            rep.y = (syl.y - sxl.y * c) * inv_nm1 * inv_var;
            rep.z = (syh.x - sxh.x * c) * inv_nm1 * inv_var;
            rep.w = (syh.y - sxh.y * c) * inv_nm1 * inv_var;

            reinterpret_cast<float4*>(out + (size_t)g * DD)[l] = rep;

            if (ib >= 2) bar_sync(BAR_EMPTY(p), NT);

            {
                const int pp  = w >> 1;
                const int sel = w & 1;
                float* base = reinterpret_cast<float*>(&rep_buf[p][pp][0]);
                base[2 * (4 * l + 0) + sel] = rep.x;
                base[2 * (4 * l + 1) + sel] = rep.y;
                base[2 * (4 * l + 2) + sel] = rep.z;
                base[2 * (4 * l + 3) + sel] = rep.w;
            }
            asm volatile("membar.cta;" ::: "memory");
            bar_arrive(BAR_FULL(p), NT);
        } else {
            // ================= CONSUMERS (warps 8..11, 128 threads) ============
            bar_sync(BAR_FULL(p), NT);

            // layer 1: thread handles hidden units ct and ct+128, 4 group-pairs
            const int ct = tid - 256;            // 0..127
            {
                const int j0 = ct, j1 = ct + 128;
                const float b0 = b1[j0], b1v = b1[j1];
                double acc[4][2];
                #pragma unroll
                for (int pp = 0; pp < 4; ++pp) {
                    acc[pp][0] = pack2(b0, b0);
                    acc[pp][1] = pack2(b1v, b1v);
                }

                #pragma unroll 4
                for (int d = 0; d < DD; d += 2) {
                    float w00 = W1[(d + 0) * HH + j0];
                    float w01 = W1[(d + 0) * HH + j1];
                    float w10 = W1[(d + 1) * HH + j0];
                    float w11 = W1[(d + 1) * HH + j1];
                    double wd00 = pack2(w00, w00);
                    double wd01 = pack2(w01, w01);
                    double wd10 = pack2(w10, w10);
                    double wd11 = pack2(w11, w11);
                    #pragma unroll
                    for (int pp = 0; pp < 4; ++pp) {
                        double2 rp = rep_buf[p][pp][d >> 1];
                        acc[pp][0] = fma2(rp.x, wd00, acc[pp][0]);
                        acc[pp][0] = fma2(rp.y, wd10, acc[pp][0]);
                        acc[pp][1] = fma2(rp.x, wd01, acc[pp][1]);
                        acc[pp][1] = fma2(rp.y, wd11, acc[pp][1]);
                    }
                }
                #pragma unroll
                for (int pp = 0; pp < 4; ++pp) {
                    float2 h0 = unpack2(acc[pp][0]);
                    float2 h1 = unpack2(acc[pp][1]);
                    h_s[2 * pp + 0][j0] = tanhf(h0.x);
                    h_s[2 * pp + 1][j0] = tanhf(h0.y);
                    h_s[2 * pp + 0][j1] = tanhf(h1.x);
                    h_s[2 * pp + 1][j1] = tanhf(h1.y);
                }
            }
            bar_sync(BAR_CONS, 128);             // h_s complete; rep reads drained
            bar_arrive(BAR_EMPTY(p), NT);        // release rep buffer p

            // layer 2 + heads: each consumer warp handles 2 groups
            {
                const int cw = wid - 8;          // 0..3
                float acc[2][KK + 2];
                #pragma unroll
                for (int gi = 0; gi < 2; ++gi)
                    #pragma unroll
                    for (int k = 0; k < KK + 2; ++k) acc[gi][k] = 0.f;

                #pragma unroll
                for (int t = 0; t < HH / 32; ++t) {
                    const int j = 32 * t + l;
                    const float h0 = h_s[2 * cw + 0][j];
                    const float h1 = h_s[2 * cw + 1][j];
                    #pragma unroll
                    for (int k = 0; k < KK + 2; ++k) {
                        const float wv = w2t[k][j];
                        acc[0][k] = fmaf(h0, wv, acc[0][k]);
                        acc[1][k] = fmaf(h1, wv, acc[1][k]);
                    }
                }
                #pragma unroll
                for (int gi = 0; gi < 2; ++gi)
                    #pragma unroll
                    for (int k = 0; k < KK + 2; ++k)
                        #pragma unroll
                        for (int o = 16; o > 0; o >>= 1)
                            acc[gi][k] += __shfl_xor_sync(0xFFFFFFFFu, acc[gi][k], o);

                if (l == 0) {
                    #pragma unroll
                    for (int gi = 0; gi < 2; ++gi) {
                        const int gl = B * GPB + 2 * cw + gi;
                        float o0 = acc[gi][0] + b2[0];
                        float o1 = acc[gi][1] + b2[1];
                        float alpha = softplus_f(o0) * (1.0f - EPSV) + EPSV;
                        float beta  = softplus_f(o1) * (1.0f - EPSV) + EPSV;

                        float ok[KK];
                        float m = -INFINITY;
                        #pragma unroll
                        for (int k = 0; k < KK; ++k) {
                            ok[k] = acc[gi][2 + k] + b2[2 + k];
                            m = fmaxf(m, ok[k]);
                        }
                        float s = 0.f;
                        #pragma unroll
                        for (int k = 0; k < KK; ++k) { ok[k] = expf(ok[k] - m); s += ok[k]; }
                        float inv = 1.0f / s;
                        #pragma unroll
                        for (int k = 0; k < KK; ++k)
                            out[OFF_MIX + (size_t)gl * KK + k] = ok[k] * inv;

                        out[OFF_SCALE + gl] = sqrtf(beta / alpha);
                        out[OFF_ALPHA + gl] = alpha;
                        out[OFF_BETA  + gl] = beta;
                    }
                }
            }
        }
    }
}

extern "C" void kernel_launch(void* const* d_in, const int* in_sizes, int n_in,
                              void* d_out, int out_size) {
    // inputs (metadata order): index, x, y, anchor_x, anchor_y, W1, b1, W2, b2
    const float* x        = (const float*)d_in[1];
    const float* y        = (const float*)d_in[2];
    const float* anchor_x = (const float*)d_in[3];
    const float* anchor_y = (const float*)d_in[4];
    const float* W1       = (const float*)d_in[5];
    const float* b1       = (const float*)d_in[6];
    const float* W2       = (const float*)d_in[7];
    const float* b2       = (const float*)d_in[8];
    float* out            = (float*)d_out;

    static bool attr_set = false;
    if (!attr_set) {
        cudaFuncSetAttribute(casync_pipeline_kernel,
                             cudaFuncAttributeMaxDynamicSharedMemorySize, SM_TOTAL);
        attr_set = true;
    }
    casync_pipeline_kernel<<<GRID_B, NT, SM_TOTAL>>>(x, y, anchor_x, anchor_y,
                                                     W1, b1, W2, b2, out);
}